// round 5
// baseline (speedup 1.0000x reference)
#include <cuda_runtime.h>
#include <cuda_bf16.h>
#include <math.h>
#include <stdint.h>

#define S_LEN 2048
#define HID   2048
#define NH    32
#define NKV   8
#define HD    64

// ---------------------------------------------------------------------------
// Scratch (device globals)
// ---------------------------------------------------------------------------
__device__ float g_q[NH * S_LEN * HD];     // pre-RoPE Q fp32
__device__ float g_k[NKV * S_LEN * HD];    // pre-RoPE K fp32

__device__ __nv_bfloat16 g_Xh[S_LEN * HID],  g_Xl[S_LEN * HID];
__device__ __nv_bfloat16 g_Wqh[HID * HID],   g_Wql[HID * HID];
__device__ __nv_bfloat16 g_Wkh[NKV*HD*HID],  g_Wkl[NKV*HD*HID];
__device__ __nv_bfloat16 g_Wvh[NKV*HD*HID],  g_Wvl[NKV*HD*HID];
__device__ __nv_bfloat16 g_Woh[HID * HID],   g_Wol[HID * HID];
__device__ __nv_bfloat16 g_Ch[S_LEN * HID],  g_Cl[S_LEN * HID];    // attn out split

__device__ __nv_bfloat16 g_qh[NH * S_LEN * HD],  g_ql[NH * S_LEN * HD];   // post-RoPE
__device__ __nv_bfloat16 g_kh[NKV * S_LEN * HD], g_kl[NKV * S_LEN * HD];
__device__ __nv_bfloat16 g_vh[NKV * S_LEN * HD], g_vl[NKV * S_LEN * HD];

// ---------------------------------------------------------------------------
// PTX helpers (plain sm_80+ features only)
// ---------------------------------------------------------------------------
__device__ __forceinline__ uint32_t s2u(const void* p) {
    uint32_t a;
    asm("{ .reg .u64 t; cvta.to.shared.u64 t, %1; cvt.u32.u64 %0, t; }" : "=r"(a) : "l"(p));
    return a;
}

__device__ __forceinline__ void ldsm4(uint32_t* r, uint32_t addr) {
    asm volatile("ldmatrix.sync.aligned.m8n8.x4.shared.b16 {%0,%1,%2,%3}, [%4];"
                 : "=r"(r[0]), "=r"(r[1]), "=r"(r[2]), "=r"(r[3]) : "r"(addr));
}

__device__ __forceinline__ void ldsm4t(uint32_t* r, uint32_t addr) {
    asm volatile("ldmatrix.sync.aligned.m8n8.x4.trans.shared.b16 {%0,%1,%2,%3}, [%4];"
                 : "=r"(r[0]), "=r"(r[1]), "=r"(r[2]), "=r"(r[3]) : "r"(addr));
}

__device__ __forceinline__ void mma16816(float* d, uint32_t a0, uint32_t a1, uint32_t a2,
                                         uint32_t a3, uint32_t b0, uint32_t b1) {
    asm volatile(
        "mma.sync.aligned.m16n8k16.row.col.f32.bf16.bf16.f32 "
        "{%0,%1,%2,%3}, {%4,%5,%6,%7}, {%8,%9}, {%0,%1,%2,%3};"
        : "+f"(d[0]), "+f"(d[1]), "+f"(d[2]), "+f"(d[3])
        : "r"(a0), "r"(a1), "r"(a2), "r"(a3), "r"(b0), "r"(b1));
}

__device__ __forceinline__ void cpa16(uint32_t saddr, const void* g) {
    asm volatile("cp.async.cg.shared.global [%0], [%1], 16;" :: "r"(saddr), "l"(g) : "memory");
}

__device__ __forceinline__ uint32_t packbf(float lo, float hi) {
    uint32_t r;
    asm("cvt.rn.bf16x2.f32 %0, %1, %2;" : "=r"(r) : "f"(hi), "f"(lo));
    return r;
}
__device__ __forceinline__ float lo_of(uint32_t p) { return __uint_as_float(p << 16); }
__device__ __forceinline__ float hi_of(uint32_t p) { return __uint_as_float(p & 0xFFFF0000u); }

// ---------------------------------------------------------------------------
// Merged fp32 -> (bf16 hi, bf16 lo) split for all 5 inputs. One launch.
// ---------------------------------------------------------------------------
#define N_X4  1048576
#define N_WQ4 1048576
#define N_WK4 262144
#define N_WV4 262144
#define N_WO4 1048576
#define N_ALL4 (N_X4 + N_WQ4 + N_WK4 + N_WV4 + N_WO4)   // 3670016 = 14336*256

__global__ __launch_bounds__(256) void split_all(const float* __restrict__ X,
                                                 const float* __restrict__ Wq,
                                                 const float* __restrict__ Wk,
                                                 const float* __restrict__ Wv,
                                                 const float* __restrict__ Wo)
{
    const int i = blockIdx.x * 256 + threadIdx.x;
    const float* src;
    __nv_bfloat16 *hi, *lo;
    int off;
    if (i < N_X4)                       { src = X;  hi = g_Xh;  lo = g_Xl;  off = i; }
    else if (i < N_X4 + N_WQ4)          { src = Wq; hi = g_Wqh; lo = g_Wql; off = i - N_X4; }
    else if (i < N_X4 + N_WQ4 + N_WK4)  { src = Wk; hi = g_Wkh; lo = g_Wkl; off = i - N_X4 - N_WQ4; }
    else if (i < N_X4 + N_WQ4 + N_WK4 + N_WV4)
                                        { src = Wv; hi = g_Wvh; lo = g_Wvl; off = i - N_X4 - N_WQ4 - N_WK4; }
    else                                { src = Wo; hi = g_Woh; lo = g_Wol; off = i - N_X4 - N_WQ4 - N_WK4 - N_WV4; }

    float4 v = ((const float4*)src)[off];
    __nv_bfloat16 h[4], l[4];
    float f[4] = {v.x, v.y, v.z, v.w};
#pragma unroll
    for (int k = 0; k < 4; ++k) {
        h[k] = __float2bfloat16(f[k]);
        l[k] = __float2bfloat16(f[k] - __bfloat162float(h[k]));
    }
    *(uint64_t*)(hi + 4 * off) = *(uint64_t*)h;
    *(uint64_t*)(lo + 4 * off) = *(uint64_t*)l;
}

// ---------------------------------------------------------------------------
// Split-bf16 HMMA GEMM (validated structure).
// MODE 0/1 -> fp32 g_q/g_k; MODE 2 -> bf16 split g_vh/g_vl; MODE 3 -> out.
// ---------------------------------------------------------------------------
template <int MODE>
__global__ __launch_bounds__(256) void hgemm_k(const float* __restrict__ bias,
                                               float* __restrict__ outp)
{
    __shared__ __align__(16) __nv_bfloat16 sm[4 * 128 * 40];

    const int t = threadIdx.x, w = t >> 5, lane = t & 31;
    const int bm = blockIdx.y * 128, bn = blockIdx.x * 128;
    const int wm = (w & 3) * 32, wn = (w >> 2) * 64;

    const __nv_bfloat16 *Ah, *Al, *Bh, *Bl;
    if (MODE == 0)      { Ah = g_Xh; Al = g_Xl; Bh = g_Wqh; Bl = g_Wql; }
    else if (MODE == 1) { Ah = g_Xh; Al = g_Xl; Bh = g_Wkh; Bl = g_Wkl; }
    else if (MODE == 2) { Ah = g_Xh; Al = g_Xl; Bh = g_Wvh; Bl = g_Wvl; }
    else                { Ah = g_Ch; Al = g_Cl; Bh = g_Woh; Bl = g_Wol; }

    const __nv_bfloat16* srcs[4] = { Ah + (size_t)bm * HID, Al + (size_t)bm * HID,
                                     Bh + (size_t)bn * HID, Bl + (size_t)bn * HID };

    const uint32_t sb = s2u(sm);
    const uint32_t a_r = lane & 15, a_c8 = (lane >> 4) << 3;
    const uint32_t b_r = ((lane >> 4) << 3) + (lane & 7), b_c8 = ((lane >> 3) & 1) << 3;

    float acc[2][8][4];
#pragma unroll
    for (int mi = 0; mi < 2; ++mi)
#pragma unroll
        for (int ni = 0; ni < 8; ++ni)
#pragma unroll
            for (int r = 0; r < 4; ++r) acc[mi][ni][r] = 0.0f;

    for (int kt = 0; kt < HID; kt += 32) {
#pragma unroll
        for (int i = 0; i < 8; ++i) {
            const int tile = i >> 1;
            const int rem = ((i & 1) << 8) + t;
            const int row = rem >> 2, q = rem & 3;
            uint4 v = *(const uint4*)(srcs[tile] + (size_t)row * HID + kt + q * 8);
            *(uint4*)(sm + tile * 5120 + row * 40 + q * 8) = v;
        }
        __syncthreads();

#pragma unroll
        for (int ks = 0; ks < 2; ++ks) {
            const uint32_t k0 = ks * 16;
            uint32_t ah[2][4], al[2][4], bh[4][4], bl[4][4];
#pragma unroll
            for (int mi = 0; mi < 2; ++mi) {
                uint32_t off = ((wm + mi * 16 + a_r) * 40 + k0 + a_c8) * 2;
                ldsm4(ah[mi], sb + 0 * 10240 + off);
                ldsm4(al[mi], sb + 1 * 10240 + off);
            }
#pragma unroll
            for (int pi = 0; pi < 4; ++pi) {
                uint32_t off = ((wn + pi * 16 + b_r) * 40 + k0 + b_c8) * 2;
                ldsm4(bh[pi], sb + 2 * 10240 + off);
                ldsm4(bl[pi], sb + 3 * 10240 + off);
            }
#pragma unroll
            for (int mi = 0; mi < 2; ++mi)
#pragma unroll
                for (int pi = 0; pi < 4; ++pi) {
#pragma unroll
                    for (int half = 0; half < 2; ++half) {
                        const int ni = pi * 2 + half;
                        const uint32_t B0 = bh[pi][half * 2], B1 = bh[pi][half * 2 + 1];
                        const uint32_t C0 = bl[pi][half * 2], C1 = bl[pi][half * 2 + 1];
                        mma16816(acc[mi][ni], ah[mi][0], ah[mi][1], ah[mi][2], ah[mi][3], B0, B1);
                        mma16816(acc[mi][ni], ah[mi][0], ah[mi][1], ah[mi][2], ah[mi][3], C0, C1);
                        mma16816(acc[mi][ni], al[mi][0], al[mi][1], al[mi][2], al[mi][3], B0, B1);
                    }
                }
        }
        __syncthreads();
    }

#pragma unroll
    for (int mi = 0; mi < 2; ++mi) {
#pragma unroll
        for (int ni = 0; ni < 8; ++ni) {
            const int col = bn + wn + ni * 8 + 2 * (lane & 3);
            float b0 = 0.f, b1 = 0.f;
            if (MODE < 3) { b0 = bias[col]; b1 = bias[col + 1]; }
#pragma unroll
            for (int rr = 0; rr < 2; ++rr) {
                const int row = bm + wm + mi * 16 + (lane >> 2) + rr * 8;
                float vx = acc[mi][ni][rr * 2 + 0] + b0;
                float vy = acc[mi][ni][rr * 2 + 1] + b1;
                if (MODE == 0 || MODE == 1) {
                    const int head = col >> 6, d = col & 63;
                    float* dst = (MODE == 0) ? g_q : g_k;
                    float2 v2 = {vx, vy};
                    *(float2*)(dst + ((size_t)head * S_LEN + row) * HD + d) = v2;
                } else if (MODE == 2) {
                    const int head = col >> 6, d = col & 63;
                    uint32_t ph = packbf(vx, vy);
                    uint32_t pl = packbf(vx - lo_of(ph), vy - hi_of(ph));
                    const size_t off = ((size_t)head * S_LEN + row) * HD + d;
                    *(uint32_t*)(g_vh + off) = ph;
                    *(uint32_t*)(g_vl + off) = pl;
                } else {
                    float2 v2 = {vx, vy};
                    *(float2*)(outp + (size_t)row * HID + col) = v2;
                }
            }
        }
    }
}

// ---------------------------------------------------------------------------
// RoPE: read fp32 g_q/g_k, write bf16 hi/lo splits.
// ---------------------------------------------------------------------------
template <int WHICH>
__global__ __launch_bounds__(256) void rope_k()
{
    const int idx = blockIdx.x * 256 + threadIdx.x;
    const int nheads = (WHICH == 0) ? NH : NKV;
    if (idx >= nheads * S_LEN * 16) return;
    const int j2 = (idx & 15) * 2;
    const int s = (idx >> 4) & (S_LEN - 1);
    const int h = idx >> 15;

    const float* src = (WHICH == 0 ? g_q : g_k) + ((size_t)h * S_LEN + s) * HD;
    float y1[2], y2[2];
#pragma unroll
    for (int e = 0; e < 2; ++e) {
        const int j = j2 + e;
        const float inv_freq = powf(10000.0f, -((float)(2 * j)) / 64.0f);
        float sn, cs;
        sincosf((float)s * inv_freq, &sn, &cs);
        const float x1 = src[j], x2 = src[j + 32];
        y1[e] = x1 * cs - x2 * sn;
        y2[e] = x2 * cs + x1 * sn;
    }
    __nv_bfloat16* dh = (WHICH == 0 ? g_qh : g_kh) + ((size_t)h * S_LEN + s) * HD;
    __nv_bfloat16* dl = (WHICH == 0 ? g_ql : g_kl) + ((size_t)h * S_LEN + s) * HD;
    uint32_t p1 = packbf(y1[0], y1[1]);
    uint32_t p2 = packbf(y2[0], y2[1]);
    *(uint32_t*)(dh + j2) = p1;
    *(uint32_t*)(dh + j2 + 32) = p2;
    *(uint32_t*)(dl + j2) = packbf(y1[0] - lo_of(p1), y1[1] - hi_of(p1));
    *(uint32_t*)(dl + j2 + 32) = packbf(y2[0] - lo_of(p2), y2[1] - hi_of(p2));
}

// ---------------------------------------------------------------------------
// HMMA flash attention with 2-stage cp.async K/V pipeline.
// CTA = (head, 64 q-rows), 4 warps x 16 rows. 3-term bf16 splits.
// smem: Qh Ql | 2 stages x (Kh Kl Vh Vl), stride-72 rows.
// ---------------------------------------------------------------------------
#define ATQ_B 9216
#define ATST_B (4 * ATQ_B)                 // 36864 per stage
#define ATTN_SMEM (2 * ATQ_B + 2 * ATST_B) // 92160

__global__ __launch_bounds__(128) void attn_k()
{
    extern __shared__ __nv_bfloat16 smb[];
    const uint32_t sb = s2u(smb);
    const int h = blockIdx.y;
    const int zz = blockIdx.x;
    const int qb = (zz & 1) ? (31 - (zz >> 1)) : (zz >> 1);
    const int kvh = h >> 2;
    const int t = threadIdx.x, w = t >> 5, lane = t & 31;

    const uint32_t QHB = 0, QLB = ATQ_B, ST0 = 2 * ATQ_B;
    const size_t kvbase = (size_t)kvh * S_LEN * HD;

    // ---- issue stage 0 <- KV tile 0 ----
    {
        const __nv_bfloat16* srcs[4] = { g_kh + kvbase, g_kl + kvbase,
                                         g_vh + kvbase, g_vl + kvbase };
#pragma unroll
        for (int ii = 0; ii < 16; ++ii) {
            const int tile = ii >> 2;
            const int rem = (ii & 3) * 128 + t;
            const int row = rem >> 3, ch = rem & 7;
            cpa16(sb + ST0 + tile * ATQ_B + (row * 72 + ch * 8) * 2,
                  srcs[tile] + row * 64 + ch * 8);
        }
        asm volatile("cp.async.commit_group;" ::: "memory");
    }

    // ---- Q tiles (regular loads) ----
    {
        const __nv_bfloat16* qh = g_qh + ((size_t)h * S_LEN + (size_t)qb * 64) * HD;
        const __nv_bfloat16* ql = g_ql + ((size_t)h * S_LEN + (size_t)qb * 64) * HD;
#pragma unroll
        for (int ii = 0; ii < 4; ++ii) {
            const int i = ii * 128 + t;
            const int row = i >> 3, ch = i & 7;
            *(uint4*)((char*)smb + QHB + (row * 72 + ch * 8) * 2) =
                *(const uint4*)(qh + row * 64 + ch * 8);
            *(uint4*)((char*)smb + QLB + (row * 72 + ch * 8) * 2) =
                *(const uint4*)(ql + row * 64 + ch * 8);
        }
    }
    __syncthreads();

    // ---- Q fragments (register-resident) ----
    const uint32_t a_r = lane & 15, a_c8 = (lane >> 4) << 3;
    const uint32_t b_r = ((lane >> 4) << 3) + (lane & 7), b_c8 = ((lane >> 3) & 1) << 3;
    uint32_t qfh[4][4], qfl[4][4];
#pragma unroll
    for (int ks = 0; ks < 4; ++ks) {
        uint32_t off = ((w * 16 + a_r) * 72 + ks * 16 + a_c8) * 2;
        ldsm4(qfh[ks], sb + QHB + off);
        ldsm4(qfl[ks], sb + QLB + off);
    }

    float oacc[8][4];
#pragma unroll
    for (int nt = 0; nt < 8; ++nt)
#pragma unroll
        for (int e = 0; e < 4; ++e) oacc[nt][e] = 0.0f;
    float m_i[2] = {-1e30f, -1e30f}, l_i[2] = {0.0f, 0.0f};

    const int grow0 = qb * 64 + w * 16 + (lane >> 2);

    for (int kb = 0; kb <= qb; ++kb) {
        const int cur = kb & 1;
        // issue next tile into other stage, then wait for current
        if (kb < qb) {
            const size_t nb = kvbase + (size_t)(kb + 1) * 64 * HD;
            const __nv_bfloat16* srcs[4] = { g_kh + nb, g_kl + nb, g_vh + nb, g_vl + nb };
            const uint32_t stb = ST0 + (cur ^ 1) * ATST_B;
#pragma unroll
            for (int ii = 0; ii < 16; ++ii) {
                const int tile = ii >> 2;
                const int rem = (ii & 3) * 128 + t;
                const int row = rem >> 3, ch = rem & 7;
                cpa16(sb + stb + tile * ATQ_B + (row * 72 + ch * 8) * 2,
                      srcs[tile] + row * 64 + ch * 8);
            }
            asm volatile("cp.async.commit_group;" ::: "memory");
            asm volatile("cp.async.wait_group 1;" ::: "memory");
        } else {
            asm volatile("cp.async.wait_group 0;" ::: "memory");
        }
        __syncthreads();

        const uint32_t KHB = ST0 + cur * ATST_B;
        const uint32_t KLB = KHB + ATQ_B;
        const uint32_t VHB = KHB + 2 * ATQ_B;
        const uint32_t VLB = KHB + 3 * ATQ_B;
        const bool diag = (kb == qb);
        const int ngmax = diag ? (w + 1) : 4;   // diagonal-tile skip

        // ---- S = Q K^T (3-term) ----
        float sacc[8][4];
#pragma unroll
        for (int nt = 0; nt < 8; ++nt)
#pragma unroll
            for (int e = 0; e < 4; ++e) sacc[nt][e] = 0.0f;

#pragma unroll
        for (int ks = 0; ks < 4; ++ks) {
            for (int np = 0; np < ngmax; ++np) {
                uint32_t BH[4], BL[4];
                uint32_t off = ((np * 16 + b_r) * 72 + ks * 16 + b_c8) * 2;
                ldsm4(BH, sb + KHB + off);
                ldsm4(BL, sb + KLB + off);
#pragma unroll
                for (int half = 0; half < 2; ++half) {
                    const int nt = np * 2 + half;
                    mma16816(sacc[nt], qfh[ks][0], qfh[ks][1], qfh[ks][2], qfh[ks][3],
                             BH[half * 2], BH[half * 2 + 1]);
                    mma16816(sacc[nt], qfh[ks][0], qfh[ks][1], qfh[ks][2], qfh[ks][3],
                             BL[half * 2], BL[half * 2 + 1]);
                    mma16816(sacc[nt], qfl[ks][0], qfl[ks][1], qfl[ks][2], qfl[ks][3],
                             BH[half * 2], BH[half * 2 + 1]);
                }
            }
        }

        // ---- online softmax ----
        float mt[2] = {-1e30f, -1e30f};
#pragma unroll
        for (int nt = 0; nt < 8; ++nt) {
#pragma unroll
            for (int e = 0; e < 4; ++e) {
                float v = sacc[nt][e] * 0.125f;
                v = fminf(fmaxf(v, -50.0f), 50.0f);
                if (diag) {
                    const int col = kb * 64 + nt * 8 + 2 * (lane & 3) + (e & 1);
                    const int row = grow0 + (e >> 1) * 8;
                    if (col > row) v = -1e30f;
                }
                sacc[nt][e] = v;
                mt[e >> 1] = fmaxf(mt[e >> 1], v);
            }
        }
#pragma unroll
        for (int o = 1; o < 4; o <<= 1) {
            mt[0] = fmaxf(mt[0], __shfl_xor_sync(0xffffffffu, mt[0], o));
            mt[1] = fmaxf(mt[1], __shfl_xor_sync(0xffffffffu, mt[1], o));
        }
        float corr[2], rs[2] = {0.0f, 0.0f};
#pragma unroll
        for (int rr = 0; rr < 2; ++rr) {
            const float mn = fmaxf(m_i[rr], mt[rr]);
            corr[rr] = __expf(m_i[rr] - mn);
            m_i[rr] = mn;
        }
#pragma unroll
        for (int nt = 0; nt < 8; ++nt)
#pragma unroll
            for (int e = 0; e < 4; ++e) {
                const float p = __expf(sacc[nt][e] - m_i[e >> 1]);
                sacc[nt][e] = p;
                rs[e >> 1] += p;
            }
#pragma unroll
        for (int o = 1; o < 4; o <<= 1) {
            rs[0] += __shfl_xor_sync(0xffffffffu, rs[0], o);
            rs[1] += __shfl_xor_sync(0xffffffffu, rs[1], o);
        }
#pragma unroll
        for (int rr = 0; rr < 2; ++rr) l_i[rr] = l_i[rr] * corr[rr] + rs[rr];
#pragma unroll
        for (int nt = 0; nt < 8; ++nt)
#pragma unroll
            for (int e = 0; e < 4; ++e) oacc[nt][e] *= corr[e >> 1];

        // ---- O += P V (3-term); skip zero P-groups on diagonal ----
        for (int ks = 0; ks < ngmax; ++ks) {
            const int L = 2 * ks, R = 2 * ks + 1;
            uint32_t ph[4], pl[4];
            ph[0] = packbf(sacc[L][0], sacc[L][1]);
            ph[1] = packbf(sacc[L][2], sacc[L][3]);
            ph[2] = packbf(sacc[R][0], sacc[R][1]);
            ph[3] = packbf(sacc[R][2], sacc[R][3]);
            pl[0] = packbf(sacc[L][0] - lo_of(ph[0]), sacc[L][1] - hi_of(ph[0]));
            pl[1] = packbf(sacc[L][2] - lo_of(ph[1]), sacc[L][3] - hi_of(ph[1]));
            pl[2] = packbf(sacc[R][0] - lo_of(ph[2]), sacc[R][1] - hi_of(ph[2]));
            pl[3] = packbf(sacc[R][2] - lo_of(ph[3]), sacc[R][3] - hi_of(ph[3]));
#pragma unroll
            for (int dp = 0; dp < 4; ++dp) {
                uint32_t VH4[4], VL4[4];
                uint32_t voff = ((ks * 16 + (lane & 7) + ((lane >> 3) & 1) * 8) * 72
                                 + dp * 16 + ((lane >> 4) << 3)) * 2;
                ldsm4t(VH4, sb + VHB + voff);
                ldsm4t(VL4, sb + VLB + voff);
#pragma unroll
                for (int half = 0; half < 2; ++half) {
                    const int nt = dp * 2 + half;
                    mma16816(oacc[nt], ph[0], ph[1], ph[2], ph[3],
                             VH4[half * 2], VH4[half * 2 + 1]);
                    mma16816(oacc[nt], ph[0], ph[1], ph[2], ph[3],
                             VL4[half * 2], VL4[half * 2 + 1]);
                    mma16816(oacc[nt], pl[0], pl[1], pl[2], pl[3],
                             VH4[half * 2], VH4[half * 2 + 1]);
                }
            }
        }
        __syncthreads();   // all reads of stage `cur` done before it is refilled
    }

    // ---- epilogue ----
    const float inv0 = 1.0f / l_i[0], inv1 = 1.0f / l_i[1];
#pragma unroll
    for (int nt = 0; nt < 8; ++nt) {
#pragma unroll
        for (int rr = 0; rr < 2; ++rr) {
            const float inv = rr ? inv1 : inv0;
            const float v0 = oacc[nt][rr * 2 + 0] * inv;
            const float v1 = oacc[nt][rr * 2 + 1] * inv;
            const int srow = qb * 64 + w * 16 + (lane >> 2) + rr * 8;
            const int col = h * 64 + nt * 8 + 2 * (lane & 3);
            uint32_t ph = packbf(v0, v1);
            uint32_t pl = packbf(v0 - lo_of(ph), v1 - hi_of(ph));
            *(uint32_t*)(g_Ch + (size_t)srow * HID + col) = ph;
            *(uint32_t*)(g_Cl + (size_t)srow * HID + col) = pl;
        }
    }
}

// ---------------------------------------------------------------------------
// Launcher
// ---------------------------------------------------------------------------
extern "C" void kernel_launch(void* const* d_in, const int* in_sizes, int n_in,
                              void* d_out, int out_size)
{
    const float* X  = (const float*)d_in[0];
    const float* Wq = (const float*)d_in[2];
    const float* bq = (const float*)d_in[3];
    const float* Wk = (const float*)d_in[4];
    const float* bk = (const float*)d_in[5];
    const float* Wv = (const float*)d_in[6];
    const float* bv = (const float*)d_in[7];
    const float* Wo = (const float*)d_in[8];
    float* out = (float*)d_out;

    split_all<<<N_ALL4 / 256, 256>>>(X, Wq, Wk, Wv, Wo);

    hgemm_k<0><<<dim3(HID / 128, S_LEN / 128), 256>>>(bq, nullptr);
    hgemm_k<1><<<dim3((NKV * HD) / 128, S_LEN / 128), 256>>>(bk, nullptr);
    hgemm_k<2><<<dim3((NKV * HD) / 128, S_LEN / 128), 256>>>(bv, nullptr);

    rope_k<0><<<(NH * S_LEN * 16) / 256, 256>>>();
    rope_k<1><<<(NKV * S_LEN * 16) / 256, 256>>>();

    cudaFuncSetAttribute(attn_k, cudaFuncAttributeMaxDynamicSharedMemorySize, ATTN_SMEM);
    attn_k<<<dim3(32, NH), 128, ATTN_SMEM>>>();

    hgemm_k<3><<<dim3(HID / 128, S_LEN / 128), 256>>>(nullptr, out);
}

// round 6
// speedup vs baseline: 1.4869x; 1.4869x over previous
#include <cuda_runtime.h>
#include <cuda_bf16.h>
#include <math.h>
#include <stdint.h>

#define S_LEN 2048
#define HID   2048
#define NH    32
#define NKV   8
#define HD    64

// ---------------------------------------------------------------------------
// Scratch (device globals)
// ---------------------------------------------------------------------------
__device__ float g_q[NH * S_LEN * HD];     // pre-RoPE Q fp32
__device__ float g_k[NKV * S_LEN * HD];    // pre-RoPE K fp32

__device__ __nv_bfloat16 g_Xh[S_LEN * HID],  g_Xl[S_LEN * HID];
__device__ __nv_bfloat16 g_Wqh[HID * HID],   g_Wql[HID * HID];
__device__ __nv_bfloat16 g_Wkh[NKV*HD*HID],  g_Wkl[NKV*HD*HID];
__device__ __nv_bfloat16 g_Wvh[NKV*HD*HID],  g_Wvl[NKV*HD*HID];
__device__ __nv_bfloat16 g_Woh[HID * HID],   g_Wol[HID * HID];
__device__ __nv_bfloat16 g_Ch[S_LEN * HID],  g_Cl[S_LEN * HID];    // attn out split

__device__ __nv_bfloat16 g_qh[NH * S_LEN * HD],  g_ql[NH * S_LEN * HD];   // post-RoPE
__device__ __nv_bfloat16 g_kh[NKV * S_LEN * HD], g_kl[NKV * S_LEN * HD];
__device__ __nv_bfloat16 g_vh[NKV * S_LEN * HD], g_vl[NKV * S_LEN * HD];

// ---------------------------------------------------------------------------
// PTX helpers (plain sm_80+ features only)
// ---------------------------------------------------------------------------
__device__ __forceinline__ uint32_t s2u(const void* p) {
    uint32_t a;
    asm("{ .reg .u64 t; cvta.to.shared.u64 t, %1; cvt.u32.u64 %0, t; }" : "=r"(a) : "l"(p));
    return a;
}

__device__ __forceinline__ void ldsm4(uint32_t* r, uint32_t addr) {
    asm volatile("ldmatrix.sync.aligned.m8n8.x4.shared.b16 {%0,%1,%2,%3}, [%4];"
                 : "=r"(r[0]), "=r"(r[1]), "=r"(r[2]), "=r"(r[3]) : "r"(addr));
}

__device__ __forceinline__ void ldsm4t(uint32_t* r, uint32_t addr) {
    asm volatile("ldmatrix.sync.aligned.m8n8.x4.trans.shared.b16 {%0,%1,%2,%3}, [%4];"
                 : "=r"(r[0]), "=r"(r[1]), "=r"(r[2]), "=r"(r[3]) : "r"(addr));
}

__device__ __forceinline__ void mma16816(float* d, uint32_t a0, uint32_t a1, uint32_t a2,
                                         uint32_t a3, uint32_t b0, uint32_t b1) {
    asm volatile(
        "mma.sync.aligned.m16n8k16.row.col.f32.bf16.bf16.f32 "
        "{%0,%1,%2,%3}, {%4,%5,%6,%7}, {%8,%9}, {%0,%1,%2,%3};"
        : "+f"(d[0]), "+f"(d[1]), "+f"(d[2]), "+f"(d[3])
        : "r"(a0), "r"(a1), "r"(a2), "r"(a3), "r"(b0), "r"(b1));
}

__device__ __forceinline__ void cpa16(uint32_t saddr, const void* g) {
    asm volatile("cp.async.cg.shared.global [%0], [%1], 16;" :: "r"(saddr), "l"(g) : "memory");
}

__device__ __forceinline__ uint32_t packbf(float lo, float hi) {
    uint32_t r;
    asm("cvt.rn.bf16x2.f32 %0, %1, %2;" : "=r"(r) : "f"(hi), "f"(lo));
    return r;
}
__device__ __forceinline__ float lo_of(uint32_t p) { return __uint_as_float(p << 16); }
__device__ __forceinline__ float hi_of(uint32_t p) { return __uint_as_float(p & 0xFFFF0000u); }

// ---------------------------------------------------------------------------
// Merged fp32 -> (bf16 hi, bf16 lo) split for all 5 inputs. One launch.
// ---------------------------------------------------------------------------
#define N_X4  1048576
#define N_WQ4 1048576
#define N_WK4 262144
#define N_WV4 262144
#define N_WO4 1048576
#define N_ALL4 (N_X4 + N_WQ4 + N_WK4 + N_WV4 + N_WO4)

__global__ __launch_bounds__(256) void split_all(const float* __restrict__ X,
                                                 const float* __restrict__ Wq,
                                                 const float* __restrict__ Wk,
                                                 const float* __restrict__ Wv,
                                                 const float* __restrict__ Wo)
{
    const int i = blockIdx.x * 256 + threadIdx.x;
    const float* src;
    __nv_bfloat16 *hi, *lo;
    int off;
    if (i < N_X4)                       { src = X;  hi = g_Xh;  lo = g_Xl;  off = i; }
    else if (i < N_X4 + N_WQ4)          { src = Wq; hi = g_Wqh; lo = g_Wql; off = i - N_X4; }
    else if (i < N_X4 + N_WQ4 + N_WK4)  { src = Wk; hi = g_Wkh; lo = g_Wkl; off = i - N_X4 - N_WQ4; }
    else if (i < N_X4 + N_WQ4 + N_WK4 + N_WV4)
                                        { src = Wv; hi = g_Wvh; lo = g_Wvl; off = i - N_X4 - N_WQ4 - N_WK4; }
    else                                { src = Wo; hi = g_Woh; lo = g_Wol; off = i - N_X4 - N_WQ4 - N_WK4 - N_WV4; }

    float4 v = ((const float4*)src)[off];
    __nv_bfloat16 h[4], l[4];
    float f[4] = {v.x, v.y, v.z, v.w};
#pragma unroll
    for (int k = 0; k < 4; ++k) {
        h[k] = __float2bfloat16(f[k]);
        l[k] = __float2bfloat16(f[k] - __bfloat162float(h[k]));
    }
    *(uint64_t*)(hi + 4 * off) = *(uint64_t*)h;
    *(uint64_t*)(lo + 4 * off) = *(uint64_t*)l;
}

// ---------------------------------------------------------------------------
// Pipelined split-bf16 HMMA GEMM, 2-stage cp.async double buffering.
// MODE 0: fused QKV — N-space [Wq(2048) | Wk(512) | Wv(512)], grid (24, 16)
// MODE 1: O projection, grid (16, 16)
// smem: 2 stages x 4 tiles x (128 x 40 halfs) = 81920 B dynamic.
// ---------------------------------------------------------------------------
#define TILE_H 5120                 // halfs per tile (128*40)
#define STAGE_H (4 * TILE_H)        // halfs per stage
#define GEMM_SMEM (2 * STAGE_H * 2) // bytes

template <int MODE>
__global__ __launch_bounds__(256) void hgemm2_k(const float* __restrict__ bq,
                                                const float* __restrict__ bk,
                                                const float* __restrict__ bv,
                                                float* __restrict__ outp)
{
    extern __shared__ __nv_bfloat16 sm[];
    const int t = threadIdx.x, w = t >> 5, lane = t & 31;
    const int bm = blockIdx.y * 128;
    const int bn = blockIdx.x * 128;
    const int wm = (w & 3) * 32, wn = (w >> 2) * 64;

    const __nv_bfloat16 *Ah, *Al, *Bh, *Bl;
    const float* bias = nullptr;
    int outsel, bcol0;
    if (MODE == 0) {
        Ah = g_Xh; Al = g_Xl;
        if (bn < 2048)      { Bh = g_Wqh; Bl = g_Wql; bias = bq; outsel = 0; bcol0 = bn; }
        else if (bn < 2560) { Bh = g_Wkh; Bl = g_Wkl; bias = bk; outsel = 1; bcol0 = bn - 2048; }
        else                { Bh = g_Wvh; Bl = g_Wvl; bias = bv; outsel = 2; bcol0 = bn - 2560; }
    } else {
        Ah = g_Ch; Al = g_Cl; Bh = g_Woh; Bl = g_Wol; outsel = 3; bcol0 = bn;
    }

    const __nv_bfloat16* srcs[4] = { Ah + (size_t)bm * HID, Al + (size_t)bm * HID,
                                     Bh + (size_t)bcol0 * HID, Bl + (size_t)bcol0 * HID };

    const uint32_t sb = s2u(sm);
    const uint32_t a_r = lane & 15, a_c8 = (lane >> 4) << 3;
    const uint32_t b_r = ((lane >> 4) << 3) + (lane & 7), b_c8 = ((lane >> 3) & 1) << 3;

    float acc[2][8][4];
#pragma unroll
    for (int mi = 0; mi < 2; ++mi)
#pragma unroll
        for (int ni = 0; ni < 8; ++ni)
#pragma unroll
            for (int r = 0; r < 4; ++r) acc[mi][ni][r] = 0.0f;

    // issue one K-tile (32 cols) of all 4 tiles into stage stg
#define ISSUE(ktv, stg)                                                              \
    {                                                                                \
        const int _kt = (ktv);                                                       \
        const uint32_t _sb0 = sb + (uint32_t)(stg) * (STAGE_H * 2);                  \
        _Pragma("unroll")                                                            \
        for (int i = 0; i < 8; ++i) {                                                \
            const int tile = i >> 1;                                                 \
            const int rem = ((i & 1) << 8) + t;                                      \
            const int row = rem >> 2, q = rem & 3;                                   \
            cpa16(_sb0 + (uint32_t)(tile * TILE_H + row * 40 + q * 8) * 2,           \
                  srcs[tile] + (size_t)row * HID + _kt + q * 8);                     \
        }                                                                            \
        asm volatile("cp.async.commit_group;" ::: "memory");                         \
    }

    ISSUE(0, 0);

    for (int it = 0; it < HID / 32; ++it) {
        const int cur = it & 1;
        if (it < HID / 32 - 1) {
            ISSUE((it + 1) * 32, cur ^ 1);
            asm volatile("cp.async.wait_group 1;" ::: "memory");
        } else {
            asm volatile("cp.async.wait_group 0;" ::: "memory");
        }
        __syncthreads();

        const uint32_t st = sb + (uint32_t)cur * (STAGE_H * 2);
#pragma unroll
        for (int ks = 0; ks < 2; ++ks) {
            const uint32_t k0 = ks * 16;
            uint32_t ah[2][4], al[2][4], bh[4][4], bl[4][4];
#pragma unroll
            for (int mi = 0; mi < 2; ++mi) {
                uint32_t off = ((wm + mi * 16 + a_r) * 40 + k0 + a_c8) * 2;
                ldsm4(ah[mi], st + 0 * (TILE_H * 2) + off);
                ldsm4(al[mi], st + 1 * (TILE_H * 2) + off);
            }
#pragma unroll
            for (int pi = 0; pi < 4; ++pi) {
                uint32_t off = ((wn + pi * 16 + b_r) * 40 + k0 + b_c8) * 2;
                ldsm4(bh[pi], st + 2 * (TILE_H * 2) + off);
                ldsm4(bl[pi], st + 3 * (TILE_H * 2) + off);
            }
#pragma unroll
            for (int mi = 0; mi < 2; ++mi)
#pragma unroll
                for (int pi = 0; pi < 4; ++pi) {
#pragma unroll
                    for (int half = 0; half < 2; ++half) {
                        const int ni = pi * 2 + half;
                        const uint32_t B0 = bh[pi][half * 2], B1 = bh[pi][half * 2 + 1];
                        const uint32_t C0 = bl[pi][half * 2], C1 = bl[pi][half * 2 + 1];
                        mma16816(acc[mi][ni], ah[mi][0], ah[mi][1], ah[mi][2], ah[mi][3], B0, B1);
                        mma16816(acc[mi][ni], ah[mi][0], ah[mi][1], ah[mi][2], ah[mi][3], C0, C1);
                        mma16816(acc[mi][ni], al[mi][0], al[mi][1], al[mi][2], al[mi][3], B0, B1);
                    }
                }
        }
        __syncthreads();
    }
#undef ISSUE

    // Epilogue
#pragma unroll
    for (int mi = 0; mi < 2; ++mi) {
#pragma unroll
        for (int ni = 0; ni < 8; ++ni) {
            const int lcol = wn + ni * 8 + 2 * (lane & 3);      // col within 128-tile
            const int col = bcol0 + lcol;                        // col within this output
            float b0 = 0.f, b1 = 0.f;
            if (MODE == 0) { b0 = bias[col]; b1 = bias[col + 1]; }
#pragma unroll
            for (int rr = 0; rr < 2; ++rr) {
                const int row = bm + wm + mi * 16 + (lane >> 2) + rr * 8;
                float vx = acc[mi][ni][rr * 2 + 0] + b0;
                float vy = acc[mi][ni][rr * 2 + 1] + b1;
                if (outsel == 0 || outsel == 1) {
                    const int head = col >> 6, d = col & 63;
                    float* dst = (outsel == 0) ? g_q : g_k;
                    float2 v2 = {vx, vy};
                    *(float2*)(dst + ((size_t)head * S_LEN + row) * HD + d) = v2;
                } else if (outsel == 2) {
                    const int head = col >> 6, d = col & 63;
                    uint32_t ph = packbf(vx, vy);
                    uint32_t pl = packbf(vx - lo_of(ph), vy - hi_of(ph));
                    const size_t off = ((size_t)head * S_LEN + row) * HD + d;
                    *(uint32_t*)(g_vh + off) = ph;
                    *(uint32_t*)(g_vl + off) = pl;
                } else {
                    float2 v2 = {vx, vy};
                    *(float2*)(outp + (size_t)row * HID + col) = v2;
                }
            }
        }
    }
}

// ---------------------------------------------------------------------------
// RoPE: read fp32 g_q/g_k, write bf16 hi/lo splits.
// ---------------------------------------------------------------------------
template <int WHICH>
__global__ __launch_bounds__(256) void rope_k()
{
    const int idx = blockIdx.x * 256 + threadIdx.x;
    const int nheads = (WHICH == 0) ? NH : NKV;
    if (idx >= nheads * S_LEN * 16) return;
    const int j2 = (idx & 15) * 2;
    const int s = (idx >> 4) & (S_LEN - 1);
    const int h = idx >> 15;

    const float* src = (WHICH == 0 ? g_q : g_k) + ((size_t)h * S_LEN + s) * HD;
    float y1[2], y2[2];
#pragma unroll
    for (int e = 0; e < 2; ++e) {
        const int j = j2 + e;
        const float inv_freq = powf(10000.0f, -((float)(2 * j)) / 64.0f);
        float sn, cs;
        sincosf((float)s * inv_freq, &sn, &cs);
        const float x1 = src[j], x2 = src[j + 32];
        y1[e] = x1 * cs - x2 * sn;
        y2[e] = x2 * cs + x1 * sn;
    }
    __nv_bfloat16* dh = (WHICH == 0 ? g_qh : g_kh) + ((size_t)h * S_LEN + s) * HD;
    __nv_bfloat16* dl = (WHICH == 0 ? g_ql : g_kl) + ((size_t)h * S_LEN + s) * HD;
    uint32_t p1 = packbf(y1[0], y1[1]);
    uint32_t p2 = packbf(y2[0], y2[1]);
    *(uint32_t*)(dh + j2) = p1;
    *(uint32_t*)(dh + j2 + 32) = p2;
    *(uint32_t*)(dl + j2) = packbf(y1[0] - lo_of(p1), y1[1] - hi_of(p1));
    *(uint32_t*)(dl + j2 + 32) = packbf(y2[0] - lo_of(p2), y2[1] - hi_of(p2));
}

// ---------------------------------------------------------------------------
// HMMA flash attention (round-4 structure: 55KB smem, plain loads, full unroll)
// ---------------------------------------------------------------------------
#define TILE_B 9216
#define ATTN_SMEM (6 * TILE_B)

__global__ __launch_bounds__(128) void attn_k()
{
    extern __shared__ __nv_bfloat16 smb[];
    const uint32_t sb = s2u(smb);
    const int h = blockIdx.y;
    const int zz = blockIdx.x;
    const int qb = (zz & 1) ? (31 - (zz >> 1)) : (zz >> 1);
    const int kvh = h >> 2;

    const int t = threadIdx.x, w = t >> 5, lane = t & 31;

    const uint32_t QHB = 0, QLB = TILE_B, KHB = 2*TILE_B, KLB = 3*TILE_B,
                   VHB = 4*TILE_B, VLB = 5*TILE_B;

    {
        const __nv_bfloat16* qh = g_qh + ((size_t)h * S_LEN + (size_t)qb * 64) * HD;
        const __nv_bfloat16* ql = g_ql + ((size_t)h * S_LEN + (size_t)qb * 64) * HD;
#pragma unroll
        for (int ii = 0; ii < 4; ++ii) {
            const int i = ii * 128 + t;
            const int row = i >> 3, ch = i & 7;
            *(uint4*)((char*)smb + QHB + (row * 72 + ch * 8) * 2) =
                *(const uint4*)(qh + row * 64 + ch * 8);
            *(uint4*)((char*)smb + QLB + (row * 72 + ch * 8) * 2) =
                *(const uint4*)(ql + row * 64 + ch * 8);
        }
    }
    __syncthreads();

    const uint32_t a_r = lane & 15, a_c8 = (lane >> 4) << 3;
    const uint32_t b_r = ((lane >> 4) << 3) + (lane & 7), b_c8 = ((lane >> 3) & 1) << 3;
    uint32_t qfh[4][4], qfl[4][4];
#pragma unroll
    for (int ks = 0; ks < 4; ++ks) {
        uint32_t off = ((w * 16 + a_r) * 72 + ks * 16 + a_c8) * 2;
        ldsm4(qfh[ks], sb + QHB + off);
        ldsm4(qfl[ks], sb + QLB + off);
    }

    float oacc[8][4];
#pragma unroll
    for (int nt = 0; nt < 8; ++nt)
#pragma unroll
        for (int e = 0; e < 4; ++e) oacc[nt][e] = 0.0f;
    float m_i[2] = {-1e30f, -1e30f}, l_i[2] = {0.0f, 0.0f};

    const int grow0 = qb * 64 + w * 16 + (lane >> 2);

    for (int kb = 0; kb <= qb; ++kb) {
        __syncthreads();
        {
            const size_t base = ((size_t)kvh * S_LEN + (size_t)kb * 64) * HD;
            const __nv_bfloat16* srcs[4] = { g_kh + base, g_kl + base, g_vh + base, g_vl + base };
            const uint32_t dstb[4] = { KHB, KLB, VHB, VLB };
#pragma unroll
            for (int ii = 0; ii < 16; ++ii) {
                const int tile = ii >> 2;
                const int rem = (ii & 3) * 128 + t;
                const int row = rem >> 3, ch = rem & 7;
                *(uint4*)((char*)smb + dstb[tile] + (row * 72 + ch * 8) * 2) =
                    *(const uint4*)(srcs[tile] + row * 64 + ch * 8);
            }
        }
        __syncthreads();

        float sacc[8][4];
#pragma unroll
        for (int nt = 0; nt < 8; ++nt)
#pragma unroll
            for (int e = 0; e < 4; ++e) sacc[nt][e] = 0.0f;

#pragma unroll
        for (int ks = 0; ks < 4; ++ks) {
#pragma unroll
            for (int np = 0; np < 4; ++np) {
                uint32_t BH[4], BL[4];
                uint32_t off = ((np * 16 + b_r) * 72 + ks * 16 + b_c8) * 2;
                ldsm4(BH, sb + KHB + off);
                ldsm4(BL, sb + KLB + off);
#pragma unroll
                for (int half = 0; half < 2; ++half) {
                    const int nt = np * 2 + half;
                    mma16816(sacc[nt], qfh[ks][0], qfh[ks][1], qfh[ks][2], qfh[ks][3],
                             BH[half * 2], BH[half * 2 + 1]);
                    mma16816(sacc[nt], qfh[ks][0], qfh[ks][1], qfh[ks][2], qfh[ks][3],
                             BL[half * 2], BL[half * 2 + 1]);
                    mma16816(sacc[nt], qfl[ks][0], qfl[ks][1], qfl[ks][2], qfl[ks][3],
                             BH[half * 2], BH[half * 2 + 1]);
                }
            }
        }

        const bool diag = (kb == qb);
        float mt[2] = {-1e30f, -1e30f};
#pragma unroll
        for (int nt = 0; nt < 8; ++nt) {
#pragma unroll
            for (int e = 0; e < 4; ++e) {
                float v = sacc[nt][e] * 0.125f;
                v = fminf(fmaxf(v, -50.0f), 50.0f);
                if (diag) {
                    const int col = kb * 64 + nt * 8 + 2 * (lane & 3) + (e & 1);
                    const int row = grow0 + (e >> 1) * 8;
                    if (col > row) v = -1e30f;
                }
                sacc[nt][e] = v;
                mt[e >> 1] = fmaxf(mt[e >> 1], v);
            }
        }
#pragma unroll
        for (int o = 1; o < 4; o <<= 1) {
            mt[0] = fmaxf(mt[0], __shfl_xor_sync(0xffffffffu, mt[0], o));
            mt[1] = fmaxf(mt[1], __shfl_xor_sync(0xffffffffu, mt[1], o));
        }
        float corr[2], rs[2] = {0.0f, 0.0f};
#pragma unroll
        for (int rr = 0; rr < 2; ++rr) {
            const float mn = fmaxf(m_i[rr], mt[rr]);
            corr[rr] = __expf(m_i[rr] - mn);
            m_i[rr] = mn;
        }
#pragma unroll
        for (int nt = 0; nt < 8; ++nt)
#pragma unroll
            for (int e = 0; e < 4; ++e) {
                const float p = __expf(sacc[nt][e] - m_i[e >> 1]);
                sacc[nt][e] = p;
                rs[e >> 1] += p;
            }
#pragma unroll
        for (int o = 1; o < 4; o <<= 1) {
            rs[0] += __shfl_xor_sync(0xffffffffu, rs[0], o);
            rs[1] += __shfl_xor_sync(0xffffffffu, rs[1], o);
        }
#pragma unroll
        for (int rr = 0; rr < 2; ++rr) l_i[rr] = l_i[rr] * corr[rr] + rs[rr];
#pragma unroll
        for (int nt = 0; nt < 8; ++nt)
#pragma unroll
            for (int e = 0; e < 4; ++e) oacc[nt][e] *= corr[e >> 1];

#pragma unroll
        for (int ks = 0; ks < 4; ++ks) {
            const int L = 2 * ks, R = 2 * ks + 1;
            uint32_t ph[4], pl[4];
            ph[0] = packbf(sacc[L][0], sacc[L][1]);
            ph[1] = packbf(sacc[L][2], sacc[L][3]);
            ph[2] = packbf(sacc[R][0], sacc[R][1]);
            ph[3] = packbf(sacc[R][2], sacc[R][3]);
            pl[0] = packbf(sacc[L][0] - lo_of(ph[0]), sacc[L][1] - hi_of(ph[0]));
            pl[1] = packbf(sacc[L][2] - lo_of(ph[1]), sacc[L][3] - hi_of(ph[1]));
            pl[2] = packbf(sacc[R][0] - lo_of(ph[2]), sacc[R][1] - hi_of(ph[2]));
            pl[3] = packbf(sacc[R][2] - lo_of(ph[3]), sacc[R][3] - hi_of(ph[3]));
#pragma unroll
            for (int dp = 0; dp < 4; ++dp) {
                uint32_t VH4[4], VL4[4];
                uint32_t voff = ((ks * 16 + (lane & 7) + ((lane >> 3) & 1) * 8) * 72
                                 + dp * 16 + ((lane >> 4) << 3)) * 2;
                ldsm4t(VH4, sb + VHB + voff);
                ldsm4t(VL4, sb + VLB + voff);
#pragma unroll
                for (int half = 0; half < 2; ++half) {
                    const int nt = dp * 2 + half;
                    mma16816(oacc[nt], ph[0], ph[1], ph[2], ph[3],
                             VH4[half * 2], VH4[half * 2 + 1]);
                    mma16816(oacc[nt], ph[0], ph[1], ph[2], ph[3],
                             VL4[half * 2], VL4[half * 2 + 1]);
                    mma16816(oacc[nt], pl[0], pl[1], pl[2], pl[3],
                             VH4[half * 2], VH4[half * 2 + 1]);
                }
            }
        }
    }

    const float inv0 = 1.0f / l_i[0], inv1 = 1.0f / l_i[1];
#pragma unroll
    for (int nt = 0; nt < 8; ++nt) {
#pragma unroll
        for (int rr = 0; rr < 2; ++rr) {
            const float inv = rr ? inv1 : inv0;
            const float v0 = oacc[nt][rr * 2 + 0] * inv;
            const float v1 = oacc[nt][rr * 2 + 1] * inv;
            const int srow = qb * 64 + w * 16 + (lane >> 2) + rr * 8;
            const int col = h * 64 + nt * 8 + 2 * (lane & 3);
            uint32_t ph = packbf(v0, v1);
            uint32_t pl = packbf(v0 - lo_of(ph), v1 - hi_of(ph));
            *(uint32_t*)(g_Ch + (size_t)srow * HID + col) = ph;
            *(uint32_t*)(g_Cl + (size_t)srow * HID + col) = pl;
        }
    }
}

// ---------------------------------------------------------------------------
// Launcher
// ---------------------------------------------------------------------------
extern "C" void kernel_launch(void* const* d_in, const int* in_sizes, int n_in,
                              void* d_out, int out_size)
{
    const float* X  = (const float*)d_in[0];
    const float* Wq = (const float*)d_in[2];
    const float* bq = (const float*)d_in[3];
    const float* Wk = (const float*)d_in[4];
    const float* bk = (const float*)d_in[5];
    const float* Wv = (const float*)d_in[6];
    const float* bv = (const float*)d_in[7];
    const float* Wo = (const float*)d_in[8];
    float* out = (float*)d_out;

    split_all<<<N_ALL4 / 256, 256>>>(X, Wq, Wk, Wv, Wo);

    cudaFuncSetAttribute(hgemm2_k<0>, cudaFuncAttributeMaxDynamicSharedMemorySize, GEMM_SMEM);
    cudaFuncSetAttribute(hgemm2_k<1>, cudaFuncAttributeMaxDynamicSharedMemorySize, GEMM_SMEM);

    // Fused Q+K+V projection: N-space 3072 columns
    hgemm2_k<0><<<dim3(24, S_LEN / 128), 256, GEMM_SMEM>>>(bq, bk, bv, nullptr);

    rope_k<0><<<(NH * S_LEN * 16) / 256, 256>>>();
    rope_k<1><<<(NKV * S_LEN * 16) / 256, 256>>>();

    cudaFuncSetAttribute(attn_k, cudaFuncAttributeMaxDynamicSharedMemorySize, ATTN_SMEM);
    attn_k<<<dim3(32, NH), 128, ATTN_SMEM>>>();

    hgemm2_k<1><<<dim3(16, S_LEN / 128), 256, GEMM_SMEM>>>(nullptr, nullptr, nullptr, out);
}

// round 7
// speedup vs baseline: 1.5327x; 1.0308x over previous
#include <cuda_runtime.h>
#include <cuda_bf16.h>
#include <math.h>
#include <stdint.h>

#define S_LEN 2048
#define HID   2048
#define NH    32
#define NKV   8
#define HD    64

// ---------------------------------------------------------------------------
// Scratch (device globals)
// ---------------------------------------------------------------------------
__device__ float g_q[NH * S_LEN * HD];     // pre-RoPE Q fp32
__device__ float g_k[NKV * S_LEN * HD];    // pre-RoPE K fp32

__device__ __nv_bfloat16 g_Xh[S_LEN * HID],  g_Xl[S_LEN * HID];
__device__ __nv_bfloat16 g_Wqh[HID * HID],   g_Wql[HID * HID];
__device__ __nv_bfloat16 g_Wkh[NKV*HD*HID],  g_Wkl[NKV*HD*HID];
__device__ __nv_bfloat16 g_Wvh[NKV*HD*HID],  g_Wvl[NKV*HD*HID];
__device__ __nv_bfloat16 g_Woh[HID * HID],   g_Wol[HID * HID];
__device__ __nv_bfloat16 g_Ch[S_LEN * HID],  g_Cl[S_LEN * HID];    // attn out split

__device__ __nv_bfloat16 g_qh[NH * S_LEN * HD],  g_ql[NH * S_LEN * HD];   // post-RoPE
__device__ __nv_bfloat16 g_kh[NKV * S_LEN * HD], g_kl[NKV * S_LEN * HD];
__device__ __nv_bfloat16 g_vh[NKV * S_LEN * HD], g_vl[NKV * S_LEN * HD];

// ---------------------------------------------------------------------------
// PTX helpers (plain sm_80+ features only)
// ---------------------------------------------------------------------------
__device__ __forceinline__ uint32_t s2u(const void* p) {
    uint32_t a;
    asm("{ .reg .u64 t; cvta.to.shared.u64 t, %1; cvt.u32.u64 %0, t; }" : "=r"(a) : "l"(p));
    return a;
}

__device__ __forceinline__ void ldsm4(uint32_t* r, uint32_t addr) {
    asm volatile("ldmatrix.sync.aligned.m8n8.x4.shared.b16 {%0,%1,%2,%3}, [%4];"
                 : "=r"(r[0]), "=r"(r[1]), "=r"(r[2]), "=r"(r[3]) : "r"(addr));
}

__device__ __forceinline__ void ldsm4t(uint32_t* r, uint32_t addr) {
    asm volatile("ldmatrix.sync.aligned.m8n8.x4.trans.shared.b16 {%0,%1,%2,%3}, [%4];"
                 : "=r"(r[0]), "=r"(r[1]), "=r"(r[2]), "=r"(r[3]) : "r"(addr));
}

__device__ __forceinline__ void mma16816(float* d, uint32_t a0, uint32_t a1, uint32_t a2,
                                         uint32_t a3, uint32_t b0, uint32_t b1) {
    asm volatile(
        "mma.sync.aligned.m16n8k16.row.col.f32.bf16.bf16.f32 "
        "{%0,%1,%2,%3}, {%4,%5,%6,%7}, {%8,%9}, {%0,%1,%2,%3};"
        : "+f"(d[0]), "+f"(d[1]), "+f"(d[2]), "+f"(d[3])
        : "r"(a0), "r"(a1), "r"(a2), "r"(a3), "r"(b0), "r"(b1));
}

__device__ __forceinline__ void cpa16(uint32_t saddr, const void* g) {
    asm volatile("cp.async.cg.shared.global [%0], [%1], 16;" :: "r"(saddr), "l"(g) : "memory");
}

__device__ __forceinline__ uint32_t packbf(float lo, float hi) {
    uint32_t r;
    asm("cvt.rn.bf16x2.f32 %0, %1, %2;" : "=r"(r) : "f"(hi), "f"(lo));
    return r;
}
__device__ __forceinline__ float lo_of(uint32_t p) { return __uint_as_float(p << 16); }
__device__ __forceinline__ float hi_of(uint32_t p) { return __uint_as_float(p & 0xFFFF0000u); }

// ---------------------------------------------------------------------------
// Merged fp32 -> (bf16 hi, bf16 lo) split for all 5 inputs. One launch.
// ---------------------------------------------------------------------------
#define N_X4  1048576
#define N_WQ4 1048576
#define N_WK4 262144
#define N_WV4 262144
#define N_WO4 1048576
#define N_ALL4 (N_X4 + N_WQ4 + N_WK4 + N_WV4 + N_WO4)

__global__ __launch_bounds__(256) void split_all(const float* __restrict__ X,
                                                 const float* __restrict__ Wq,
                                                 const float* __restrict__ Wk,
                                                 const float* __restrict__ Wv,
                                                 const float* __restrict__ Wo)
{
    const int i = blockIdx.x * 256 + threadIdx.x;
    const float* src;
    __nv_bfloat16 *hi, *lo;
    int off;
    if (i < N_X4)                       { src = X;  hi = g_Xh;  lo = g_Xl;  off = i; }
    else if (i < N_X4 + N_WQ4)          { src = Wq; hi = g_Wqh; lo = g_Wql; off = i - N_X4; }
    else if (i < N_X4 + N_WQ4 + N_WK4)  { src = Wk; hi = g_Wkh; lo = g_Wkl; off = i - N_X4 - N_WQ4; }
    else if (i < N_X4 + N_WQ4 + N_WK4 + N_WV4)
                                        { src = Wv; hi = g_Wvh; lo = g_Wvl; off = i - N_X4 - N_WQ4 - N_WK4; }
    else                                { src = Wo; hi = g_Woh; lo = g_Wol; off = i - N_X4 - N_WQ4 - N_WK4 - N_WV4; }

    float4 v = ((const float4*)src)[off];
    __nv_bfloat16 h[4], l[4];
    float f[4] = {v.x, v.y, v.z, v.w};
#pragma unroll
    for (int k = 0; k < 4; ++k) {
        h[k] = __float2bfloat16(f[k]);
        l[k] = __float2bfloat16(f[k] - __bfloat162float(h[k]));
    }
    *(uint64_t*)(hi + 4 * off) = *(uint64_t*)h;
    *(uint64_t*)(lo + 4 * off) = *(uint64_t*)l;
}

// ---------------------------------------------------------------------------
// Pipelined split-bf16 HMMA GEMM, 2-stage cp.async double buffering.
// MODE 0: fused QKV — N-space [Wq(2048) | Wk(512) | Wv(512)], grid (24, 16)
// MODE 1: O projection, grid (16, 16)
// ---------------------------------------------------------------------------
#define TILE_H 5120
#define STAGE_H (4 * TILE_H)
#define GEMM_SMEM (2 * STAGE_H * 2)

template <int MODE>
__global__ __launch_bounds__(256) void hgemm2_k(const float* __restrict__ bq,
                                                const float* __restrict__ bk,
                                                const float* __restrict__ bv,
                                                float* __restrict__ outp)
{
    extern __shared__ __nv_bfloat16 sm[];
    const int t = threadIdx.x, w = t >> 5, lane = t & 31;
    const int bm = blockIdx.y * 128;
    const int bn = blockIdx.x * 128;
    const int wm = (w & 3) * 32, wn = (w >> 2) * 64;

    const __nv_bfloat16 *Ah, *Al, *Bh, *Bl;
    const float* bias = nullptr;
    int outsel, bcol0;
    if (MODE == 0) {
        Ah = g_Xh; Al = g_Xl;
        if (bn < 2048)      { Bh = g_Wqh; Bl = g_Wql; bias = bq; outsel = 0; bcol0 = bn; }
        else if (bn < 2560) { Bh = g_Wkh; Bl = g_Wkl; bias = bk; outsel = 1; bcol0 = bn - 2048; }
        else                { Bh = g_Wvh; Bl = g_Wvl; bias = bv; outsel = 2; bcol0 = bn - 2560; }
    } else {
        Ah = g_Ch; Al = g_Cl; Bh = g_Woh; Bl = g_Wol; outsel = 3; bcol0 = bn;
    }

    const __nv_bfloat16* srcs[4] = { Ah + (size_t)bm * HID, Al + (size_t)bm * HID,
                                     Bh + (size_t)bcol0 * HID, Bl + (size_t)bcol0 * HID };

    const uint32_t sb = s2u(sm);
    const uint32_t a_r = lane & 15, a_c8 = (lane >> 4) << 3;
    const uint32_t b_r = ((lane >> 4) << 3) + (lane & 7), b_c8 = ((lane >> 3) & 1) << 3;

    float acc[2][8][4];
#pragma unroll
    for (int mi = 0; mi < 2; ++mi)
#pragma unroll
        for (int ni = 0; ni < 8; ++ni)
#pragma unroll
            for (int r = 0; r < 4; ++r) acc[mi][ni][r] = 0.0f;

#define ISSUE(ktv, stg)                                                              \
    {                                                                                \
        const int _kt = (ktv);                                                       \
        const uint32_t _sb0 = sb + (uint32_t)(stg) * (STAGE_H * 2);                  \
        _Pragma("unroll")                                                            \
        for (int i = 0; i < 8; ++i) {                                                \
            const int tile = i >> 1;                                                 \
            const int rem = ((i & 1) << 8) + t;                                      \
            const int row = rem >> 2, q = rem & 3;                                   \
            cpa16(_sb0 + (uint32_t)(tile * TILE_H + row * 40 + q * 8) * 2,           \
                  srcs[tile] + (size_t)row * HID + _kt + q * 8);                     \
        }                                                                            \
        asm volatile("cp.async.commit_group;" ::: "memory");                         \
    }

    ISSUE(0, 0);

    for (int it = 0; it < HID / 32; ++it) {
        const int cur = it & 1;
        if (it < HID / 32 - 1) {
            ISSUE((it + 1) * 32, cur ^ 1);
            asm volatile("cp.async.wait_group 1;" ::: "memory");
        } else {
            asm volatile("cp.async.wait_group 0;" ::: "memory");
        }
        __syncthreads();

        const uint32_t st = sb + (uint32_t)cur * (STAGE_H * 2);
#pragma unroll
        for (int ks = 0; ks < 2; ++ks) {
            const uint32_t k0 = ks * 16;
            uint32_t ah[2][4], al[2][4], bh[4][4], bl[4][4];
#pragma unroll
            for (int mi = 0; mi < 2; ++mi) {
                uint32_t off = ((wm + mi * 16 + a_r) * 40 + k0 + a_c8) * 2;
                ldsm4(ah[mi], st + 0 * (TILE_H * 2) + off);
                ldsm4(al[mi], st + 1 * (TILE_H * 2) + off);
            }
#pragma unroll
            for (int pi = 0; pi < 4; ++pi) {
                uint32_t off = ((wn + pi * 16 + b_r) * 40 + k0 + b_c8) * 2;
                ldsm4(bh[pi], st + 2 * (TILE_H * 2) + off);
                ldsm4(bl[pi], st + 3 * (TILE_H * 2) + off);
            }
#pragma unroll
            for (int mi = 0; mi < 2; ++mi)
#pragma unroll
                for (int pi = 0; pi < 4; ++pi) {
#pragma unroll
                    for (int half = 0; half < 2; ++half) {
                        const int ni = pi * 2 + half;
                        const uint32_t B0 = bh[pi][half * 2], B1 = bh[pi][half * 2 + 1];
                        const uint32_t C0 = bl[pi][half * 2], C1 = bl[pi][half * 2 + 1];
                        mma16816(acc[mi][ni], ah[mi][0], ah[mi][1], ah[mi][2], ah[mi][3], B0, B1);
                        mma16816(acc[mi][ni], ah[mi][0], ah[mi][1], ah[mi][2], ah[mi][3], C0, C1);
                        mma16816(acc[mi][ni], al[mi][0], al[mi][1], al[mi][2], al[mi][3], B0, B1);
                    }
                }
        }
        __syncthreads();
    }
#undef ISSUE

#pragma unroll
    for (int mi = 0; mi < 2; ++mi) {
#pragma unroll
        for (int ni = 0; ni < 8; ++ni) {
            const int lcol = wn + ni * 8 + 2 * (lane & 3);
            const int col = bcol0 + lcol;
            float b0 = 0.f, b1 = 0.f;
            if (MODE == 0) { b0 = bias[col]; b1 = bias[col + 1]; }
#pragma unroll
            for (int rr = 0; rr < 2; ++rr) {
                const int row = bm + wm + mi * 16 + (lane >> 2) + rr * 8;
                float vx = acc[mi][ni][rr * 2 + 0] + b0;
                float vy = acc[mi][ni][rr * 2 + 1] + b1;
                if (outsel == 0 || outsel == 1) {
                    const int head = col >> 6, d = col & 63;
                    float* dst = (outsel == 0) ? g_q : g_k;
                    float2 v2 = {vx, vy};
                    *(float2*)(dst + ((size_t)head * S_LEN + row) * HD + d) = v2;
                } else if (outsel == 2) {
                    const int head = col >> 6, d = col & 63;
                    uint32_t ph = packbf(vx, vy);
                    uint32_t pl = packbf(vx - lo_of(ph), vy - hi_of(ph));
                    const size_t off = ((size_t)head * S_LEN + row) * HD + d;
                    *(uint32_t*)(g_vh + off) = ph;
                    *(uint32_t*)(g_vl + off) = pl;
                } else {
                    float2 v2 = {vx, vy};
                    *(float2*)(outp + (size_t)row * HID + col) = v2;
                }
            }
        }
    }
}

// ---------------------------------------------------------------------------
// RoPE for Q and K in one launch.
// ---------------------------------------------------------------------------
#define ROPE_Q_N (NH * S_LEN * 16)
#define ROPE_K_N (NKV * S_LEN * 16)

__global__ __launch_bounds__(256) void rope_all()
{
    int idx = blockIdx.x * 256 + threadIdx.x;
    const float* srcb;
    __nv_bfloat16 *dhb, *dlb;
    if (idx < ROPE_Q_N) { srcb = g_q; dhb = g_qh; dlb = g_ql; }
    else                { srcb = g_k; dhb = g_kh; dlb = g_kl; idx -= ROPE_Q_N; }

    const int j2 = (idx & 15) * 2;
    const int s = (idx >> 4) & (S_LEN - 1);
    const int h = idx >> 15;
    const size_t base = ((size_t)h * S_LEN + s) * HD;

    const float* src = srcb + base;
    float y1[2], y2[2];
#pragma unroll
    for (int e = 0; e < 2; ++e) {
        const int j = j2 + e;
        const float inv_freq = powf(10000.0f, -((float)(2 * j)) / 64.0f);
        float sn, cs;
        sincosf((float)s * inv_freq, &sn, &cs);
        const float x1 = src[j], x2 = src[j + 32];
        y1[e] = x1 * cs - x2 * sn;
        y2[e] = x2 * cs + x1 * sn;
    }
    __nv_bfloat16* dh = dhb + base;
    __nv_bfloat16* dl = dlb + base;
    uint32_t p1 = packbf(y1[0], y1[1]);
    uint32_t p2 = packbf(y2[0], y2[1]);
    *(uint32_t*)(dh + j2) = p1;
    *(uint32_t*)(dh + j2 + 32) = p2;
    *(uint32_t*)(dl + j2) = packbf(y1[0] - lo_of(p1), y1[1] - hi_of(p1));
    *(uint32_t*)(dl + j2 + 32) = packbf(y2[0] - lo_of(p2), y2[1] - hi_of(p2));
}

// ---------------------------------------------------------------------------
// HMMA flash attention, split pipeline:
//   K: 2 cp.async stages (issued one tile ahead, overlapping softmax+PV)
//   V: single buffer, issued at top of iteration, waited after softmax
// smem: Qh Ql (18432) | Kstage0 (18432) | Kstage1 (18432) | Vh Vl (18432)
// ---------------------------------------------------------------------------
#define TILE_B 9216
#define AT_Q   0
#define AT_K0  (2 * TILE_B)
#define AT_K1  (4 * TILE_B)
#define AT_V   (6 * TILE_B)
#define ATTN_SMEM (8 * TILE_B)     // 73728

__global__ __launch_bounds__(128, 3) void attn_k()
{
    extern __shared__ __nv_bfloat16 smb[];
    const uint32_t sb = s2u(smb);
    const int h = blockIdx.y;
    const int zz = blockIdx.x;
    const int qb = (zz & 1) ? (31 - (zz >> 1)) : (zz >> 1);
    const int kvh = h >> 2;

    const int t = threadIdx.x, w = t >> 5, lane = t & 31;
    const size_t kvbase = (size_t)kvh * S_LEN * HD;

    // copy one 2-tile pair (hi+lo, 64x64 bf16 each) via cp.async: 8 uint4/thread
#define CPKV(dstoff, srch, srcl)                                                    \
    {                                                                               \
        _Pragma("unroll")                                                           \
        for (int ii = 0; ii < 8; ++ii) {                                            \
            const int tile = ii >> 2;                                               \
            const int rem = (ii & 3) * 128 + t;                                     \
            const int row = rem >> 3, ch = rem & 7;                                 \
            cpa16(sb + (dstoff) + tile * TILE_B + (row * 72 + ch * 8) * 2,          \
                  (tile ? (srcl) : (srch)) + row * 64 + ch * 8);                    \
        }                                                                           \
        asm volatile("cp.async.commit_group;" ::: "memory");                        \
    }

    // prologue: K tile 0 -> stage 0
    CPKV(AT_K0, g_kh + kvbase, g_kl + kvbase);

    // Q tiles (plain loads)
    {
        const __nv_bfloat16* qh = g_qh + ((size_t)h * S_LEN + (size_t)qb * 64) * HD;
        const __nv_bfloat16* ql = g_ql + ((size_t)h * S_LEN + (size_t)qb * 64) * HD;
#pragma unroll
        for (int ii = 0; ii < 4; ++ii) {
            const int i = ii * 128 + t;
            const int row = i >> 3, ch = i & 7;
            *(uint4*)((char*)smb + AT_Q + (row * 72 + ch * 8) * 2) =
                *(const uint4*)(qh + row * 64 + ch * 8);
            *(uint4*)((char*)smb + AT_Q + TILE_B + (row * 72 + ch * 8) * 2) =
                *(const uint4*)(ql + row * 64 + ch * 8);
        }
    }
    __syncthreads();

    const uint32_t a_r = lane & 15, a_c8 = (lane >> 4) << 3;
    const uint32_t b_r = ((lane >> 4) << 3) + (lane & 7), b_c8 = ((lane >> 3) & 1) << 3;
    uint32_t qfh[4][4], qfl[4][4];
#pragma unroll
    for (int ks = 0; ks < 4; ++ks) {
        uint32_t off = ((w * 16 + a_r) * 72 + ks * 16 + a_c8) * 2;
        ldsm4(qfh[ks], sb + AT_Q + off);
        ldsm4(qfl[ks], sb + AT_Q + TILE_B + off);
    }

    float oacc[8][4];
#pragma unroll
    for (int nt = 0; nt < 8; ++nt)
#pragma unroll
        for (int e = 0; e < 4; ++e) oacc[nt][e] = 0.0f;
    float m_i[2] = {-1e30f, -1e30f}, l_i[2] = {0.0f, 0.0f};

    const int grow0 = qb * 64 + w * 16 + (lane >> 2);

    for (int kb = 0; kb <= qb; ++kb) {
        const uint32_t KHB = (kb & 1) ? AT_K1 : AT_K0;
        const uint32_t KLB = KHB + TILE_B;
        // V buffer free (prev PV done via end-of-loop / top sync)
        __syncthreads();
        {
            const size_t vb = kvbase + (size_t)kb * 64 * HD;
            CPKV(AT_V, g_vh + vb, g_vl + vb);                 // V group (newest)
        }
        asm volatile("cp.async.wait_group 1;" ::: "memory");  // K(kb) arrived
        __syncthreads();

        // ---- S = Q K^T (3-term) ----
        float sacc[8][4];
#pragma unroll
        for (int nt = 0; nt < 8; ++nt)
#pragma unroll
            for (int e = 0; e < 4; ++e) sacc[nt][e] = 0.0f;

#pragma unroll
        for (int ks = 0; ks < 4; ++ks) {
#pragma unroll
            for (int np = 0; np < 4; ++np) {
                uint32_t BH[4], BL[4];
                uint32_t off = ((np * 16 + b_r) * 72 + ks * 16 + b_c8) * 2;
                ldsm4(BH, sb + KHB + off);
                ldsm4(BL, sb + KLB + off);
#pragma unroll
                for (int half = 0; half < 2; ++half) {
                    const int nt = np * 2 + half;
                    mma16816(sacc[nt], qfh[ks][0], qfh[ks][1], qfh[ks][2], qfh[ks][3],
                             BH[half * 2], BH[half * 2 + 1]);
                    mma16816(sacc[nt], qfh[ks][0], qfh[ks][1], qfh[ks][2], qfh[ks][3],
                             BL[half * 2], BL[half * 2 + 1]);
                    mma16816(sacc[nt], qfl[ks][0], qfl[ks][1], qfl[ks][2], qfl[ks][3],
                             BH[half * 2], BH[half * 2 + 1]);
                }
            }
        }

        // issue K(kb+1) into other stage (readers of that stage finished last iter)
        if (kb < qb) {
            const size_t nb = kvbase + (size_t)(kb + 1) * 64 * HD;
            const uint32_t nstage = (kb & 1) ? AT_K0 : AT_K1;
            CPKV(nstage, g_kh + nb, g_kl + nb);
        }

        // ---- online softmax ----
        const bool diag = (kb == qb);
        float mt[2] = {-1e30f, -1e30f};
#pragma unroll
        for (int nt = 0; nt < 8; ++nt) {
#pragma unroll
            for (int e = 0; e < 4; ++e) {
                float v = sacc[nt][e] * 0.125f;
                v = fminf(fmaxf(v, -50.0f), 50.0f);
                if (diag) {
                    const int col = kb * 64 + nt * 8 + 2 * (lane & 3) + (e & 1);
                    const int row = grow0 + (e >> 1) * 8;
                    if (col > row) v = -1e30f;
                }
                sacc[nt][e] = v;
                mt[e >> 1] = fmaxf(mt[e >> 1], v);
            }
        }
#pragma unroll
        for (int o = 1; o < 4; o <<= 1) {
            mt[0] = fmaxf(mt[0], __shfl_xor_sync(0xffffffffu, mt[0], o));
            mt[1] = fmaxf(mt[1], __shfl_xor_sync(0xffffffffu, mt[1], o));
        }
        float corr[2], rs[2] = {0.0f, 0.0f};
#pragma unroll
        for (int rr = 0; rr < 2; ++rr) {
            const float mn = fmaxf(m_i[rr], mt[rr]);
            corr[rr] = __expf(m_i[rr] - mn);
            m_i[rr] = mn;
        }
#pragma unroll
        for (int nt = 0; nt < 8; ++nt)
#pragma unroll
            for (int e = 0; e < 4; ++e) {
                const float p = __expf(sacc[nt][e] - m_i[e >> 1]);
                sacc[nt][e] = p;
                rs[e >> 1] += p;
            }
#pragma unroll
        for (int o = 1; o < 4; o <<= 1) {
            rs[0] += __shfl_xor_sync(0xffffffffu, rs[0], o);
            rs[1] += __shfl_xor_sync(0xffffffffu, rs[1], o);
        }
#pragma unroll
        for (int rr = 0; rr < 2; ++rr) l_i[rr] = l_i[rr] * corr[rr] + rs[rr];
#pragma unroll
        for (int nt = 0; nt < 8; ++nt)
#pragma unroll
            for (int e = 0; e < 4; ++e) oacc[nt][e] *= corr[e >> 1];

        // ---- wait V (K(kb+1) may stay in flight), then PV ----
        if (kb < qb) asm volatile("cp.async.wait_group 1;" ::: "memory");
        else         asm volatile("cp.async.wait_group 0;" ::: "memory");
        __syncthreads();

#pragma unroll
        for (int ks = 0; ks < 4; ++ks) {
            const int L = 2 * ks, R = 2 * ks + 1;
            uint32_t ph[4], pl[4];
            ph[0] = packbf(sacc[L][0], sacc[L][1]);
            ph[1] = packbf(sacc[L][2], sacc[L][3]);
            ph[2] = packbf(sacc[R][0], sacc[R][1]);
            ph[3] = packbf(sacc[R][2], sacc[R][3]);
            pl[0] = packbf(sacc[L][0] - lo_of(ph[0]), sacc[L][1] - hi_of(ph[0]));
            pl[1] = packbf(sacc[L][2] - lo_of(ph[1]), sacc[L][3] - hi_of(ph[1]));
            pl[2] = packbf(sacc[R][0] - lo_of(ph[2]), sacc[R][1] - hi_of(ph[2]));
            pl[3] = packbf(sacc[R][2] - lo_of(ph[3]), sacc[R][3] - hi_of(ph[3]));
#pragma unroll
            for (int dp = 0; dp < 4; ++dp) {
                uint32_t VH4[4], VL4[4];
                uint32_t voff = ((ks * 16 + (lane & 7) + ((lane >> 3) & 1) * 8) * 72
                                 + dp * 16 + ((lane >> 4) << 3)) * 2;
                ldsm4t(VH4, sb + AT_V + voff);
                ldsm4t(VL4, sb + AT_V + TILE_B + voff);
#pragma unroll
                for (int half = 0; half < 2; ++half) {
                    const int nt = dp * 2 + half;
                    mma16816(oacc[nt], ph[0], ph[1], ph[2], ph[3],
                             VH4[half * 2], VH4[half * 2 + 1]);
                    mma16816(oacc[nt], ph[0], ph[1], ph[2], ph[3],
                             VL4[half * 2], VL4[half * 2 + 1]);
                    mma16816(oacc[nt], pl[0], pl[1], pl[2], pl[3],
                             VH4[half * 2], VH4[half * 2 + 1]);
                }
            }
        }
    }
#undef CPKV

    const float inv0 = 1.0f / l_i[0], inv1 = 1.0f / l_i[1];
#pragma unroll
    for (int nt = 0; nt < 8; ++nt) {
#pragma unroll
        for (int rr = 0; rr < 2; ++rr) {
            const float inv = rr ? inv1 : inv0;
            const float v0 = oacc[nt][rr * 2 + 0] * inv;
            const float v1 = oacc[nt][rr * 2 + 1] * inv;
            const int srow = qb * 64 + w * 16 + (lane >> 2) + rr * 8;
            const int col = h * 64 + nt * 8 + 2 * (lane & 3);
            uint32_t ph = packbf(v0, v1);
            uint32_t pl = packbf(v0 - lo_of(ph), v1 - hi_of(ph));
            *(uint32_t*)(g_Ch + (size_t)srow * HID + col) = ph;
            *(uint32_t*)(g_Cl + (size_t)srow * HID + col) = pl;
        }
    }
}

// ---------------------------------------------------------------------------
// Launcher
// ---------------------------------------------------------------------------
extern "C" void kernel_launch(void* const* d_in, const int* in_sizes, int n_in,
                              void* d_out, int out_size)
{
    const float* X  = (const float*)d_in[0];
    const float* Wq = (const float*)d_in[2];
    const float* bq = (const float*)d_in[3];
    const float* Wk = (const float*)d_in[4];
    const float* bk = (const float*)d_in[5];
    const float* Wv = (const float*)d_in[6];
    const float* bv = (const float*)d_in[7];
    const float* Wo = (const float*)d_in[8];
    float* out = (float*)d_out;

    split_all<<<N_ALL4 / 256, 256>>>(X, Wq, Wk, Wv, Wo);

    cudaFuncSetAttribute(hgemm2_k<0>, cudaFuncAttributeMaxDynamicSharedMemorySize, GEMM_SMEM);
    cudaFuncSetAttribute(hgemm2_k<1>, cudaFuncAttributeMaxDynamicSharedMemorySize, GEMM_SMEM);

    hgemm2_k<0><<<dim3(24, S_LEN / 128), 256, GEMM_SMEM>>>(bq, bk, bv, nullptr);

    rope_all<<<(ROPE_Q_N + ROPE_K_N) / 256, 256>>>();

    cudaFuncSetAttribute(attn_k, cudaFuncAttributeMaxDynamicSharedMemorySize, ATTN_SMEM);
    attn_k<<<dim3(32, NH), 128, ATTN_SMEM>>>();

    hgemm2_k<1><<<dim3(16, S_LEN / 128), 256, GEMM_SMEM>>>(nullptr, nullptr, nullptr, out);
}